// round 15
// baseline (speedup 1.0000x reference)
#include <cuda_runtime.h>
#include <cuda_bf16.h>
#include <cuda.h>
#include <cstdint>
#include <cmath>

// ======================= problem sizes =======================
#define MT     4096      // tokens = B*S
#define HID    4096
#define INTER  11008

// ======================= PTX helpers (portable sm_90 subset) =========
__device__ __forceinline__ uint32_t smem_to_u32(const void* smem_ptr) {
    uint32_t addr;
    asm("{ .reg .u64 tmp; cvta.to.shared.u64 tmp, %1; cvt.u32.u64 %0, tmp; }"
        : "=r"(addr) : "l"(smem_ptr));
    return addr;
}

#define MBARRIER_INIT(mbar, count) \
    asm volatile("mbarrier.init.shared.b64 [%0], %1;" \
        :: "r"((uint32_t)(mbar)), "r"((uint32_t)(count)) : "memory")

#define MBARRIER_EXPECT_TX(mbar, tx_bytes) \
    asm volatile("mbarrier.arrive.expect_tx.shared.b64 _, [%0], %1;" \
        :: "r"((uint32_t)(mbar)), "r"((uint32_t)(tx_bytes)) : "memory")

#define MBARRIER_ARRIVE(mbar) \
    asm volatile("mbarrier.arrive.shared.b64 _, [%0];" \
        :: "r"((uint32_t)(mbar)) : "memory")

#define MBARRIER_WAIT_PARITY(mbar, parity) do { \
    uint32_t _mbar = (uint32_t)(mbar); \
    uint32_t _parity = (uint32_t)(parity); \
    uint32_t _done; \
    asm volatile( \
        "{\n\t" \
        ".reg .pred p;\n\t" \
        "mbarrier.try_wait.parity.acquire.cta.shared::cta.b64 p, [%1], %2;\n\t" \
        "selp.b32 %0, 1, 0, p;\n\t" \
        "}" \
        : "=r"(_done) : "r"(_mbar), "r"(_parity) : "memory"); \
    if (!_done) { \
        asm volatile( \
            "{\n\t" \
            ".reg .pred P1;\n\t" \
            "WAIT_LOOP_%=:\n\t" \
            "mbarrier.try_wait.parity.acquire.cta.shared::cta.b64 P1, [%0], %1, 0x989680;\n\t" \
            "@P1 bra.uni WAIT_DONE_%=;\n\t" \
            "bra.uni WAIT_LOOP_%=;\n\t" \
            "WAIT_DONE_%=:\n\t" \
            "}" \
            :: "r"(_mbar), "r"(_parity) : "memory"); \
    } \
} while(0)

#define MBARRIER_WAIT_PARITY_RELAXED(mbar, parity) do { \
    uint32_t _mbar = (uint32_t)(mbar); \
    uint32_t _parity = (uint32_t)(parity); \
    uint32_t _done; \
    asm volatile( \
        "{\n\t" \
        ".reg .pred p;\n\t" \
        "mbarrier.try_wait.parity.relaxed.cta.shared::cta.b64 p, [%1], %2, 0x989680;\n\t" \
        "selp.b32 %0, 1, 0, p;\n\t" \
        "}" \
        : "=r"(_done) : "r"(_mbar), "r"(_parity) : "memory"); \
    if (!_done) { \
        asm volatile( \
            "{\n\t" \
            ".reg .pred P1;\n\t" \
            "WAIT_LOOP_%=:\n\t" \
            "mbarrier.try_wait.parity.relaxed.cta.shared::cta.b64 P1, [%0], %1, 0x989680;\n\t" \
            "@P1 bra.uni WAIT_DONE_%=;\n\t" \
            "bra.uni WAIT_LOOP_%=;\n\t" \
            "WAIT_DONE_%=:\n\t" \
            "}" \
            :: "r"(_mbar), "r"(_parity) : "memory"); \
    } \
} while(0)

__device__ __forceinline__ void tma_load_2d(uint32_t dst, const CUtensorMap* map,
                                            int cx, int cy, uint32_t mbar) {
    asm volatile(
        "cp.async.bulk.tensor.2d.shared::cta.global.tile.mbarrier::complete_tx::bytes "
        "[%0], [%1, {%2, %3}], [%4];"
        :: "r"(dst), "l"(map), "r"(cx), "r"(cy), "r"(mbar) : "memory");
}

__device__ __forceinline__ void ldsm4(uint32_t* r, uint32_t addr) {
    asm volatile("ldmatrix.sync.aligned.m8n8.x4.shared.b16 {%0,%1,%2,%3}, [%4];"
        : "=r"(r[0]), "=r"(r[1]), "=r"(r[2]), "=r"(r[3]) : "r"(addr));
}

__device__ __forceinline__ void mma_bf16(float* c, const uint32_t* a,
                                         uint32_t b0, uint32_t b1) {
    asm volatile("mma.sync.aligned.m16n8k16.row.col.f32.bf16.bf16.f32 "
        "{%0,%1,%2,%3}, {%4,%5,%6,%7}, {%8,%9}, {%0,%1,%2,%3};"
        : "+f"(c[0]), "+f"(c[1]), "+f"(c[2]), "+f"(c[3])
        : "r"(a[0]), "r"(a[1]), "r"(a[2]), "r"(a[3]), "r"(b0), "r"(b1));
}

// ======================= device scratch ======================
__device__ __nv_bfloat16 g_xq[(size_t)MT * HID];
__device__ __nv_bfloat16 g_wgq[(size_t)INTER * HID];
__device__ __nv_bfloat16 g_wuq[(size_t)INTER * HID];
__device__ __nv_bfloat16 g_wdq[(size_t)HID * INTER];
__device__ float         g_h[(size_t)MT * INTER];
__device__ __nv_bfloat16 g_hq[(size_t)MT * INTER];
__device__ float         g_sx[MT];
__device__ float         g_swg[INTER];
__device__ float         g_swu[INTER];
__device__ float         g_swd[HID];
__device__ float         g_sh[MT];
__device__ unsigned int  g_rowmax[MT];

// ======================= quantize kernels ====================
__device__ __forceinline__ uint32_t pack_q2(float a, float b, float sc) {
    float qa = fminf(fmaxf(rintf(a / sc), -128.f), 127.f);
    float qb = fminf(fmaxf(rintf(b / sc), -128.f), 127.f);
    __nv_bfloat162 p = __floats2bfloat162_rn(qa, qb);
    return *(uint32_t*)&p;
}

template<int COLS>
__device__ __forceinline__ void quant_row_body(const float* __restrict__ in,
                                               __nv_bfloat16* __restrict__ q,
                                               float* __restrict__ scale, int row) {
    constexpr int N4  = COLS / 4;
    constexpr int PER = (N4 + 255) / 256;
    __shared__ float red[8];
    int tid = threadIdx.x;
    const float4* r4 = (const float4*)(in + (size_t)row * COLS);
    float4 v[PER];
    float m = 0.f;
    #pragma unroll
    for (int i = 0; i < PER; ++i) {
        int c = tid + i * 256;
        if (c < N4) {
            v[i] = r4[c];
            m = fmaxf(m, fmaxf(fmaxf(fabsf(v[i].x), fabsf(v[i].y)),
                               fmaxf(fabsf(v[i].z), fabsf(v[i].w))));
        }
    }
    #pragma unroll
    for (int d = 16; d > 0; d >>= 1) m = fmaxf(m, __shfl_xor_sync(0xFFFFFFFFu, m, d));
    if ((tid & 31) == 0) red[tid >> 5] = m;
    __syncthreads();
    m = red[0];
    #pragma unroll
    for (int w = 1; w < 8; ++w) m = fmaxf(m, red[w]);
    float sc = fmaxf(m / 127.0f, 1e-8f);
    if (tid == 0) scale[row] = sc;
    uint2* q2 = (uint2*)(q + (size_t)row * COLS);
    #pragma unroll
    for (int i = 0; i < PER; ++i) {
        int c = tid + i * 256;
        if (c < N4) {
            uint2 o;
            o.x = pack_q2(v[i].x, v[i].y, sc);
            o.y = pack_q2(v[i].z, v[i].w, sc);
            q2[c] = o;
        }
    }
}

// ALL input quantization in one launch: x, w_gate, w_up (4096-col) + w_down (11008-col)
__global__ __launch_bounds__(256)
void quant_all_kernel(const float* __restrict__ x,  const float* __restrict__ wg,
                      const float* __restrict__ wu, const float* __restrict__ wd,
                      __nv_bfloat16* xq, __nv_bfloat16* wgq, __nv_bfloat16* wuq,
                      __nv_bfloat16* wdq,
                      float* sx, float* swg, float* swu, float* swd) {
    int row = blockIdx.x;
    if (row < MT)                   quant_row_body<HID>(x,  xq,  sx,  row);
    else if (row < MT + INTER)      quant_row_body<HID>(wg, wgq, swg, row - MT);
    else if (row < MT + 2 * INTER)  quant_row_body<HID>(wu, wuq, swu, row - MT - INTER);
    else                            quant_row_body<INTER>(wd, wdq, swd, row - MT - 2 * INTER);
}

// h quant: scale precomputed via rowmax -> no reduction; 4 blocks per row
__global__ __launch_bounds__(256)
void quant_h_kernel(const float* __restrict__ h,
                    const unsigned int* __restrict__ rowmax,
                    __nv_bfloat16* __restrict__ hq,
                    float* __restrict__ sh) {
    int row = blockIdx.x;
    float sc = fmaxf(__uint_as_float(rowmax[row]) / 127.0f, 1e-8f);
    if (threadIdx.x == 0 && blockIdx.y == 0) sh[row] = sc;
    const float4* r4 = (const float4*)(h + (size_t)row * INTER);
    uint2* q2 = (uint2*)(hq + (size_t)row * INTER);
    int chunk = (INTER >> 2) / 4;
    int c0 = blockIdx.y * chunk;
    for (int c = c0 + threadIdx.x; c < c0 + chunk; c += 256) {
        float4 v = r4[c];
        uint2 o;
        o.x = pack_q2(v.x, v.y, sc);
        o.y = pack_q2(v.z, v.w, sc);
        q2[c] = o;
    }
}

// ======================= GEMM kernel =========================
// Non-persistent: one CTA per 128x128 tile. 16 math warps (mw=4 x nw=4)
// + 1 producer warp, 544 threads. Each warp 32x32 per bop. TKK=128 both modes
// (8 k16 chunks per stage, sub-buffer select kk>>2) -> minimal stage waits.
// MODE 0: gate/up (2 B ops). Stage: [A0 A1 Bg0 Bg1 Bu0 Bu1] = 96KB, 2 stages.
// MODE 1: down proj (1 B).   Stage: [A0 A1 B0 B1]           = 64KB, 3 stages.

#define GEMM_THREADS 544
#define TKK          128

template<int MODE>
__global__ __launch_bounds__(GEMM_THREADS, 1)
void gemm_kernel(const __grid_constant__ CUtensorMap tma_a,
                 const __grid_constant__ CUtensorMap tma_b0,
                 const __grid_constant__ CUtensorMap tma_b1,
                 int k_iters,
                 const float* __restrict__ s_a,
                 const float* __restrict__ s_b0,
                 const float* __restrict__ s_b1,
                 float* __restrict__ outp,
                 unsigned int* __restrict__ rowmax,
                 int out_ld)
{
    constexpr int      STAGES      = (MODE == 0) ? 2 : 3;
    constexpr uint32_t STAGE_BYTES = (MODE == 0) ? 98304u : 65536u;

    extern __shared__ char smem[];
    uint32_t sb     = smem_to_u32(smem);
    uint32_t fullb  = sb;            // STAGES x 8B
    uint32_t emptyb = sb + 32u;      // STAGES x 8B
    uint32_t data   = (sb + 64u + 1023u) & ~1023u;

    int tid  = threadIdx.x;
    int wid  = tid >> 5;
    int lane = tid & 31;

    if (tid == 0) {
        #pragma unroll
        for (int s = 0; s < STAGES; s++) {
            MBARRIER_INIT(fullb  + 8u * s, 1);
            MBARRIER_INIT(emptyb + 8u * s, 16);
        }
    }
    __syncthreads();

    // ---------------- producer warp ----------------
    if (wid == 16) {
        if (lane == 0) {
            int mbase = blockIdx.x * 128;
            int nbase = blockIdx.y * 128;
            int st = 0, ph = 1;
            for (int it = 0; it < k_iters; ++it) {
                MBARRIER_WAIT_PARITY_RELAXED(emptyb + 8u * st, ph);
                MBARRIER_EXPECT_TX(fullb + 8u * st, STAGE_BYTES);
                uint32_t d0 = data + st * STAGE_BYTES;
                uint32_t mb = fullb + 8u * st;
                int k0 = it * TKK, k1 = it * TKK + 64;
                tma_load_2d(d0,           &tma_a,  k0, mbase, mb);
                tma_load_2d(d0 + 16384u, &tma_a,  k1, mbase, mb);
                tma_load_2d(d0 + 32768u, &tma_b0, k0, nbase, mb);
                tma_load_2d(d0 + 49152u, &tma_b0, k1, nbase, mb);
                if (MODE == 0) {
                    tma_load_2d(d0 + 65536u, &tma_b1, k0, nbase, mb);
                    tma_load_2d(d0 + 81920u, &tma_b1, k1, nbase, mb);
                }
                if (++st == STAGES) { st = 0; ph ^= 1; }
            }
        }
        return;
    }

    // ---------------- math warps 0..15 (mw=4 x nw=4) ----------------
    constexpr int NBOP  = (MODE == 0) ? 2 : 1;
    constexpr int NPAIR = 2;
    constexpr int MA    = 2;

    int warpM = wid >> 2;            // 0..3, 32 rows each
    int warpN = wid & 3;             // 0..3, 32 cols each

    int rA = warpM * 32 + (lane & 15);
    uint32_t rawA = (uint32_t)rA * 128u;
    uint32_t xorA = (uint32_t)(rA & 7) * 16u;
    uint32_t klA  = ((uint32_t)(lane >> 4) & 1u) * 16u;

    uint32_t rbrow = (uint32_t)((lane & 7) + ((lane >> 4) << 3));
    uint32_t rawB  = rbrow * 128u;
    uint32_t xorB  = (uint32_t)(lane & 7) * 16u;
    uint32_t klB   = ((uint32_t)(lane >> 3) & 1u) * 16u;

    uint32_t nrowoff = (uint32_t)(warpN * 32) * 128u;

    float acc[NBOP][MA][NPAIR * 2][4];
    #pragma unroll
    for (int b = 0; b < NBOP; ++b)
        #pragma unroll
        for (int m = 0; m < MA; ++m)
            #pragma unroll
            for (int a = 0; a < NPAIR * 2; ++a)
                #pragma unroll
                for (int j = 0; j < 4; ++j) acc[b][m][a][j] = 0.f;

    int st = 0, ph = 0;
    for (int it = 0; it < k_iters; ++it) {
        MBARRIER_WAIT_PARITY(fullb + 8u * st, ph);
        uint32_t sbase = data + st * STAGE_BYTES;
        #pragma unroll
        for (int kk = 0; kk < 8; ++kk) {
            uint32_t sub  = (uint32_t)(kk >> 2) * 16384u;   // 64-col sub-buffer
            uint32_t kin  = (uint32_t)(kk & 3) * 32u;
            uint32_t kbA = kin + klA;
            uint32_t af[MA][4];
            #pragma unroll
            for (int m = 0; m < MA; ++m)
                ldsm4(af[m], sbase + sub + rawA + (uint32_t)m * 2048u + (kbA ^ xorA));
            uint32_t kbB = kin + klB;
            #pragma unroll
            for (int b = 0; b < NBOP; ++b) {
                uint32_t bb = sbase + 32768u + (uint32_t)b * 32768u + sub + nrowoff + rawB;
                #pragma unroll
                for (int p = 0; p < NPAIR; ++p) {
                    uint32_t br[4];
                    ldsm4(br, bb + (uint32_t)p * 2048u + (kbB ^ xorB));
                    #pragma unroll
                    for (int m = 0; m < MA; ++m) {
                        mma_bf16(acc[b][m][2 * p],     af[m], br[0], br[1]);
                        mma_bf16(acc[b][m][2 * p + 1], af[m], br[2], br[3]);
                    }
                }
            }
        }
        if (lane == 0) MBARRIER_ARRIVE(emptyb + 8u * st);
        if (++st == STAGES) { st = 0; ph ^= 1; }
    }

    // ---------------- epilogue ----------------
    int mrowbase = blockIdx.x * 128 + warpM * 32;
    int ncolbase = blockIdx.y * 128 + warpN * 32;
    int qr = lane >> 2;
    int qc = (lane & 3) * 2;

    #pragma unroll
    for (int matom = 0; matom < MA; ++matom) {
        int r0 = mrowbase + matom * 16 + qr;
        int r1 = r0 + 8;
        float sa0 = s_a[r0], sa1 = s_a[r1];
        if constexpr (MODE == 0) {
            float amax0 = 0.f, amax1 = 0.f;
            #pragma unroll
            for (int a = 0; a < 4; ++a) {
                int n0 = ncolbase + a * 8 + qc;
                float sg0 = s_b0[n0], sg1 = s_b0[n0 + 1];
                float su0 = s_b1[n0], su1 = s_b1[n0 + 1];
                const float* cg = acc[0][matom][a];
                const float* cu = acc[1][matom][a];
                float g00 = cg[0] * sa0 * sg0, g01 = cg[1] * sa0 * sg1;
                float g10 = cg[2] * sa1 * sg0, g11 = cg[3] * sa1 * sg1;
                float u00 = cu[0] * sa0 * su0, u01 = cu[1] * sa0 * su1;
                float u10 = cu[2] * sa1 * su0, u11 = cu[3] * sa1 * su1;
                float h00 = (g00 / (1.f + expf(-g00))) * u00;
                float h01 = (g01 / (1.f + expf(-g01))) * u01;
                float h10 = (g10 / (1.f + expf(-g10))) * u10;
                float h11 = (g11 / (1.f + expf(-g11))) * u11;
                *(float2*)(outp + (size_t)r0 * out_ld + n0) = make_float2(h00, h01);
                *(float2*)(outp + (size_t)r1 * out_ld + n0) = make_float2(h10, h11);
                amax0 = fmaxf(amax0, fmaxf(fabsf(h00), fabsf(h01)));
                amax1 = fmaxf(amax1, fmaxf(fabsf(h10), fabsf(h11)));
            }
            #pragma unroll
            for (int d = 1; d < 4; d <<= 1) {
                amax0 = fmaxf(amax0, __shfl_xor_sync(0xFFFFFFFFu, amax0, d));
                amax1 = fmaxf(amax1, __shfl_xor_sync(0xFFFFFFFFu, amax1, d));
            }
            if ((lane & 3) == 0) {
                atomicMax(rowmax + r0, __float_as_uint(amax0));
                atomicMax(rowmax + r1, __float_as_uint(amax1));
            }
        } else {
            #pragma unroll
            for (int a = 0; a < 4; ++a) {
                int n0 = ncolbase + a * 8 + qc;
                float sw0 = s_b0[n0], sw1 = s_b0[n0 + 1];
                const float* c = acc[0][matom][a];
                *(float2*)(outp + (size_t)r0 * out_ld + n0) =
                    make_float2(c[0] * sa0 * sw0, c[1] * sa0 * sw1);
                *(float2*)(outp + (size_t)r1 * out_ld + n0) =
                    make_float2(c[2] * sa1 * sw0, c[3] * sa1 * sw1);
            }
        }
    }
}

#define GEMM_SMEM0 (2 * 98304u + 2048u)
#define GEMM_SMEM1 (3 * 65536u + 2048u)

// ======================= host side ===========================
typedef CUresult (*tmap_encode_fn)(
    CUtensorMap*, CUtensorMapDataType, cuuint32_t, void*,
    const cuuint64_t*, const cuuint64_t*, const cuuint32_t*, const cuuint32_t*,
    CUtensorMapInterleave, CUtensorMapSwizzle, CUtensorMapL2promotion,
    CUtensorMapFloatOOBfill);

static void make_map(tmap_encode_fn fn, CUtensorMap* map, void* ptr,
                     uint64_t d0, uint64_t d1, uint32_t box_rows) {
    cuuint64_t dims[2]    = {(cuuint64_t)d0, (cuuint64_t)d1};
    cuuint64_t strides[1] = {(cuuint64_t)(d0 * 2)};            // bf16
    cuuint32_t box[2]     = {64u, box_rows};                   // 64 bf16 = 128B (SW128)
    cuuint32_t es[2]      = {1u, 1u};
    fn(map, CU_TENSOR_MAP_DATA_TYPE_BFLOAT16, 2, ptr, dims, strides, box, es,
       CU_TENSOR_MAP_INTERLEAVE_NONE, CU_TENSOR_MAP_SWIZZLE_128B,
       CU_TENSOR_MAP_L2_PROMOTION_L2_128B, CU_TENSOR_MAP_FLOAT_OOB_FILL_NONE);
}

extern "C" void kernel_launch(void* const* d_in, const int* in_sizes, int n_in,
                              void* d_out, int out_size) {
    const float* x  = (const float*)d_in[0];
    const float* wg = (const float*)d_in[1];
    const float* wu = (const float*)d_in[2];
    const float* wd = (const float*)d_in[3];
    float* out = (float*)d_out;

    void *p_xq, *p_wgq, *p_wuq, *p_wdq, *p_h, *p_hq;
    void *p_sx, *p_swg, *p_swu, *p_swd, *p_sh, *p_rm;
    cudaGetSymbolAddress(&p_xq, g_xq);
    cudaGetSymbolAddress(&p_wgq, g_wgq);
    cudaGetSymbolAddress(&p_wuq, g_wuq);
    cudaGetSymbolAddress(&p_wdq, g_wdq);
    cudaGetSymbolAddress(&p_h, g_h);
    cudaGetSymbolAddress(&p_hq, g_hq);
    cudaGetSymbolAddress(&p_sx, g_sx);
    cudaGetSymbolAddress(&p_swg, g_swg);
    cudaGetSymbolAddress(&p_swu, g_swu);
    cudaGetSymbolAddress(&p_swd, g_swd);
    cudaGetSymbolAddress(&p_sh, g_sh);
    cudaGetSymbolAddress(&p_rm, g_rowmax);

    void* fn = nullptr;
    cudaDriverEntryPointQueryResult qres;
    cudaGetDriverEntryPointByVersion("cuTensorMapEncodeTiled", &fn, 12000,
                                     cudaEnableDefault, &qres);
    tmap_encode_fn encode = (tmap_encode_fn)fn;

    CUtensorMap mXQ, mWG, mWU, mHQ, mWD;
    make_map(encode, &mXQ, p_xq,  HID,   MT,    128); // GEMM1 A
    make_map(encode, &mWG, p_wgq, HID,   INTER, 128); // GEMM1 Bgate
    make_map(encode, &mWU, p_wuq, HID,   INTER, 128); // GEMM1 Bup
    make_map(encode, &mHQ, p_hq,  INTER, MT,    128); // GEMM2 A
    make_map(encode, &mWD, p_wdq, INTER, HID,   128); // GEMM2 B

    cudaMemsetAsync(p_rm, 0, MT * sizeof(unsigned int));

    // single merged quant launch for all inputs
    quant_all_kernel<<<MT + 2 * INTER + HID, 256>>>(
        x, wg, wu, wd,
        (__nv_bfloat16*)p_xq, (__nv_bfloat16*)p_wgq, (__nv_bfloat16*)p_wuq,
        (__nv_bfloat16*)p_wdq,
        (float*)p_sx, (float*)p_swg, (float*)p_swu, (float*)p_swd);

    cudaFuncSetAttribute(gemm_kernel<0>, cudaFuncAttributeMaxDynamicSharedMemorySize, GEMM_SMEM0);
    cudaFuncSetAttribute(gemm_kernel<1>, cudaFuncAttributeMaxDynamicSharedMemorySize, GEMM_SMEM1);

    // GEMM1: fused gate/up + SwiGLU -> h. grid 32 x 86, TKK=128, k_iters=32
    gemm_kernel<0><<<dim3(MT / 128, INTER / 128), GEMM_THREADS, GEMM_SMEM0>>>(
        mXQ, mWG, mWU, HID / TKK,
        (const float*)p_sx, (const float*)p_swg, (const float*)p_swu,
        (float*)p_h, (unsigned int*)p_rm, INTER);

    quant_h_kernel<<<dim3(MT, 4), 256>>>((const float*)p_h, (const unsigned int*)p_rm,
                                         (__nv_bfloat16*)p_hq, (float*)p_sh);

    // GEMM2: down proj. grid 32 x 32, TKK=128, k_iters=86
    gemm_kernel<1><<<dim3(MT / 128, HID / 128), GEMM_THREADS, GEMM_SMEM1>>>(
        mHQ, mWD, mWD, INTER / TKK,
        (const float*)p_sh, (const float*)p_swd, (const float*)p_swd,
        out, nullptr, HID);
}

// round 16
// speedup vs baseline: 1.5116x; 1.5116x over previous
#include <cuda_runtime.h>
#include <cuda_bf16.h>
#include <cuda.h>
#include <cstdint>
#include <cmath>

// ======================= problem sizes =======================
#define MT     4096      // tokens = B*S
#define HID    4096
#define INTER  11008

// ======================= PTX helpers (portable sm_90 subset) =========
__device__ __forceinline__ uint32_t smem_to_u32(const void* smem_ptr) {
    uint32_t addr;
    asm("{ .reg .u64 tmp; cvta.to.shared.u64 tmp, %1; cvt.u32.u64 %0, tmp; }"
        : "=r"(addr) : "l"(smem_ptr));
    return addr;
}

#define MBARRIER_INIT(mbar, count) \
    asm volatile("mbarrier.init.shared.b64 [%0], %1;" \
        :: "r"((uint32_t)(mbar)), "r"((uint32_t)(count)) : "memory")

#define MBARRIER_EXPECT_TX(mbar, tx_bytes) \
    asm volatile("mbarrier.arrive.expect_tx.shared.b64 _, [%0], %1;" \
        :: "r"((uint32_t)(mbar)), "r"((uint32_t)(tx_bytes)) : "memory")

#define MBARRIER_ARRIVE(mbar) \
    asm volatile("mbarrier.arrive.shared.b64 _, [%0];" \
        :: "r"((uint32_t)(mbar)) : "memory")

#define MBARRIER_WAIT_PARITY(mbar, parity) do { \
    uint32_t _mbar = (uint32_t)(mbar); \
    uint32_t _parity = (uint32_t)(parity); \
    uint32_t _done; \
    asm volatile( \
        "{\n\t" \
        ".reg .pred p;\n\t" \
        "mbarrier.try_wait.parity.acquire.cta.shared::cta.b64 p, [%1], %2;\n\t" \
        "selp.b32 %0, 1, 0, p;\n\t" \
        "}" \
        : "=r"(_done) : "r"(_mbar), "r"(_parity) : "memory"); \
    if (!_done) { \
        asm volatile( \
            "{\n\t" \
            ".reg .pred P1;\n\t" \
            "WAIT_LOOP_%=:\n\t" \
            "mbarrier.try_wait.parity.acquire.cta.shared::cta.b64 P1, [%0], %1, 0x989680;\n\t" \
            "@P1 bra.uni WAIT_DONE_%=;\n\t" \
            "bra.uni WAIT_LOOP_%=;\n\t" \
            "WAIT_DONE_%=:\n\t" \
            "}" \
            :: "r"(_mbar), "r"(_parity) : "memory"); \
    } \
} while(0)

#define MBARRIER_WAIT_PARITY_RELAXED(mbar, parity) do { \
    uint32_t _mbar = (uint32_t)(mbar); \
    uint32_t _parity = (uint32_t)(parity); \
    uint32_t _done; \
    asm volatile( \
        "{\n\t" \
        ".reg .pred p;\n\t" \
        "mbarrier.try_wait.parity.relaxed.cta.shared::cta.b64 p, [%1], %2, 0x989680;\n\t" \
        "selp.b32 %0, 1, 0, p;\n\t" \
        "}" \
        : "=r"(_done) : "r"(_mbar), "r"(_parity) : "memory"); \
    if (!_done) { \
        asm volatile( \
            "{\n\t" \
            ".reg .pred P1;\n\t" \
            "WAIT_LOOP_%=:\n\t" \
            "mbarrier.try_wait.parity.relaxed.cta.shared::cta.b64 P1, [%0], %1, 0x989680;\n\t" \
            "@P1 bra.uni WAIT_DONE_%=;\n\t" \
            "bra.uni WAIT_LOOP_%=;\n\t" \
            "WAIT_DONE_%=:\n\t" \
            "}" \
            :: "r"(_mbar), "r"(_parity) : "memory"); \
    } \
} while(0)

__device__ __forceinline__ void tma_load_2d(uint32_t dst, const CUtensorMap* map,
                                            int cx, int cy, uint32_t mbar) {
    asm volatile(
        "cp.async.bulk.tensor.2d.shared::cta.global.tile.mbarrier::complete_tx::bytes "
        "[%0], [%1, {%2, %3}], [%4];"
        :: "r"(dst), "l"(map), "r"(cx), "r"(cy), "r"(mbar) : "memory");
}

__device__ __forceinline__ void ldsm4(uint32_t* r, uint32_t addr) {
    asm volatile("ldmatrix.sync.aligned.m8n8.x4.shared.b16 {%0,%1,%2,%3}, [%4];"
        : "=r"(r[0]), "=r"(r[1]), "=r"(r[2]), "=r"(r[3]) : "r"(addr));
}

__device__ __forceinline__ void mma_bf16(float* c, const uint32_t* a,
                                         uint32_t b0, uint32_t b1) {
    asm volatile("mma.sync.aligned.m16n8k16.row.col.f32.bf16.bf16.f32 "
        "{%0,%1,%2,%3}, {%4,%5,%6,%7}, {%8,%9}, {%0,%1,%2,%3};"
        : "+f"(c[0]), "+f"(c[1]), "+f"(c[2]), "+f"(c[3])
        : "r"(a[0]), "r"(a[1]), "r"(a[2]), "r"(a[3]), "r"(b0), "r"(b1));
}

// ======================= device scratch ======================
__device__ __nv_bfloat16 g_xq[(size_t)MT * HID];
__device__ __nv_bfloat16 g_wgq[(size_t)INTER * HID];
__device__ __nv_bfloat16 g_wuq[(size_t)INTER * HID];
__device__ __nv_bfloat16 g_wdq[(size_t)HID * INTER];
__device__ float         g_h[(size_t)MT * INTER];
__device__ __nv_bfloat16 g_hq[(size_t)MT * INTER];
__device__ float         g_sx[MT];
__device__ float         g_swg[INTER];
__device__ float         g_swu[INTER];
__device__ float         g_swd[HID];
__device__ float         g_sh[MT];
__device__ unsigned int  g_rowmax[MT];

// ======================= quantize kernels ====================
__device__ __forceinline__ uint32_t pack_q2(float a, float b, float sc) {
    float qa = fminf(fmaxf(rintf(a / sc), -128.f), 127.f);
    float qb = fminf(fmaxf(rintf(b / sc), -128.f), 127.f);
    __nv_bfloat162 p = __floats2bfloat162_rn(qa, qb);
    return *(uint32_t*)&p;
}

template<int COLS>
__device__ __forceinline__ void quant_row_body(const float* __restrict__ in,
                                               __nv_bfloat16* __restrict__ q,
                                               float* __restrict__ scale, int row) {
    constexpr int N4  = COLS / 4;
    constexpr int PER = (N4 + 255) / 256;
    __shared__ float red[8];
    int tid = threadIdx.x;
    const float4* r4 = (const float4*)(in + (size_t)row * COLS);
    float4 v[PER];
    float m = 0.f;
    #pragma unroll
    for (int i = 0; i < PER; ++i) {
        int c = tid + i * 256;
        if (c < N4) {
            v[i] = r4[c];
            m = fmaxf(m, fmaxf(fmaxf(fabsf(v[i].x), fabsf(v[i].y)),
                               fmaxf(fabsf(v[i].z), fabsf(v[i].w))));
        }
    }
    #pragma unroll
    for (int d = 16; d > 0; d >>= 1) m = fmaxf(m, __shfl_xor_sync(0xFFFFFFFFu, m, d));
    if ((tid & 31) == 0) red[tid >> 5] = m;
    __syncthreads();
    m = red[0];
    #pragma unroll
    for (int w = 1; w < 8; ++w) m = fmaxf(m, red[w]);
    float sc = fmaxf(m / 127.0f, 1e-8f);
    if (tid == 0) scale[row] = sc;
    uint2* q2 = (uint2*)(q + (size_t)row * COLS);
    #pragma unroll
    for (int i = 0; i < PER; ++i) {
        int c = tid + i * 256;
        if (c < N4) {
            uint2 o;
            o.x = pack_q2(v[i].x, v[i].y, sc);
            o.y = pack_q2(v[i].z, v[i].w, sc);
            q2[c] = o;
        }
    }
}

// ALL input quantization in one launch: x, w_gate, w_up (4096-col) + w_down (11008-col)
__global__ __launch_bounds__(256)
void quant_all_kernel(const float* __restrict__ x,  const float* __restrict__ wg,
                      const float* __restrict__ wu, const float* __restrict__ wd,
                      __nv_bfloat16* xq, __nv_bfloat16* wgq, __nv_bfloat16* wuq,
                      __nv_bfloat16* wdq,
                      float* sx, float* swg, float* swu, float* swd) {
    int row = blockIdx.x;
    if (row < MT)                   quant_row_body<HID>(x,  xq,  sx,  row);
    else if (row < MT + INTER)      quant_row_body<HID>(wg, wgq, swg, row - MT);
    else if (row < MT + 2 * INTER)  quant_row_body<HID>(wu, wuq, swu, row - MT - INTER);
    else                            quant_row_body<INTER>(wd, wdq, swd, row - MT - 2 * INTER);
}

// h quant: scale precomputed via rowmax -> no reduction; 4 blocks per row
__global__ __launch_bounds__(256)
void quant_h_kernel(const float* __restrict__ h,
                    const unsigned int* __restrict__ rowmax,
                    __nv_bfloat16* __restrict__ hq,
                    float* __restrict__ sh) {
    int row = blockIdx.x;
    float sc = fmaxf(__uint_as_float(rowmax[row]) / 127.0f, 1e-8f);
    if (threadIdx.x == 0 && blockIdx.y == 0) sh[row] = sc;
    const float4* r4 = (const float4*)(h + (size_t)row * INTER);
    uint2* q2 = (uint2*)(hq + (size_t)row * INTER);
    int chunk = (INTER >> 2) / 4;
    int c0 = blockIdx.y * chunk;
    for (int c = c0 + threadIdx.x; c < c0 + chunk; c += 256) {
        float4 v = r4[c];
        uint2 o;
        o.x = pack_q2(v.x, v.y, sc);
        o.y = pack_q2(v.z, v.w, sc);
        q2[c] = o;
    }
}

// ======================= GEMM kernel (R14 best config) =========
// Non-persistent: one CTA per 128x128 tile. 16 math warps (mw=4 x nw=4)
// + 1 producer warp, 544 threads. Each warp 32x32 per bop.
// MODE 0: gate/up (2 B ops). TKK=64.  Stage: [A 16K][Bg 16K][Bu 16K], 4 stages.
// MODE 1: down proj (1 B).   TKK=128. Stage: [A0 16K][A1 16K][B0 16K][B1 16K],
//         3 stages (64KB each) -> half as many stage waits per tile.

#define GEMM_THREADS 544

template<int MODE>
__global__ __launch_bounds__(GEMM_THREADS, 1)
void gemm_kernel(const __grid_constant__ CUtensorMap tma_a,
                 const __grid_constant__ CUtensorMap tma_b0,
                 const __grid_constant__ CUtensorMap tma_b1,
                 int k_iters,
                 const float* __restrict__ s_a,
                 const float* __restrict__ s_b0,
                 const float* __restrict__ s_b1,
                 float* __restrict__ outp,
                 unsigned int* __restrict__ rowmax,
                 int out_ld)
{
    constexpr int      STAGES      = (MODE == 0) ? 4 : 3;
    constexpr uint32_t STAGE_BYTES = (MODE == 0) ? 49152u : 65536u;
    constexpr int      TKK         = (MODE == 0) ? 64 : 128;
    constexpr int      KCHUNKS     = (MODE == 0) ? 4 : 8;

    extern __shared__ char smem[];
    uint32_t sb     = smem_to_u32(smem);
    uint32_t fullb  = sb;            // STAGES x 8B
    uint32_t emptyb = sb + 32u;      // STAGES x 8B
    uint32_t data   = (sb + 64u + 1023u) & ~1023u;

    int tid  = threadIdx.x;
    int wid  = tid >> 5;
    int lane = tid & 31;

    if (tid == 0) {
        #pragma unroll
        for (int s = 0; s < STAGES; s++) {
            MBARRIER_INIT(fullb  + 8u * s, 1);
            MBARRIER_INIT(emptyb + 8u * s, 16);
        }
    }
    __syncthreads();

    // ---------------- producer warp ----------------
    if (wid == 16) {
        if (lane == 0) {
            int mbase = blockIdx.x * 128;
            int nbase = blockIdx.y * 128;
            int st = 0, ph = 1;
            for (int it = 0; it < k_iters; ++it) {
                MBARRIER_WAIT_PARITY_RELAXED(emptyb + 8u * st, ph);
                MBARRIER_EXPECT_TX(fullb + 8u * st, STAGE_BYTES);
                uint32_t d0 = data + st * STAGE_BYTES;
                uint32_t mb = fullb + 8u * st;
                if (MODE == 0) {
                    tma_load_2d(d0,           &tma_a,  it * TKK, mbase, mb);
                    tma_load_2d(d0 + 16384u, &tma_b0, it * TKK, nbase, mb);
                    tma_load_2d(d0 + 32768u, &tma_b1, it * TKK, nbase, mb);
                } else {
                    tma_load_2d(d0,           &tma_a,  it * TKK,      mbase, mb);
                    tma_load_2d(d0 + 16384u, &tma_a,  it * TKK + 64, mbase, mb);
                    tma_load_2d(d0 + 32768u, &tma_b0, it * TKK,      nbase, mb);
                    tma_load_2d(d0 + 49152u, &tma_b0, it * TKK + 64, nbase, mb);
                }
                if (++st == STAGES) { st = 0; ph ^= 1; }
            }
        }
        return;
    }

    // ---------------- math warps 0..15 (mw=4 x nw=4) ----------------
    constexpr int NBOP  = (MODE == 0) ? 2 : 1;
    constexpr int NPAIR = 2;
    constexpr int MA    = 2;

    int warpM = wid >> 2;            // 0..3, 32 rows each
    int warpN = wid & 3;             // 0..3, 32 cols each

    int rA = warpM * 32 + (lane & 15);
    uint32_t rawA = (uint32_t)rA * 128u;
    uint32_t xorA = (uint32_t)(rA & 7) * 16u;
    uint32_t klA  = ((uint32_t)(lane >> 4) & 1u) * 16u;

    uint32_t rbrow = (uint32_t)((lane & 7) + ((lane >> 4) << 3));
    uint32_t rawB  = rbrow * 128u;
    uint32_t xorB  = (uint32_t)(lane & 7) * 16u;
    uint32_t klB   = ((uint32_t)(lane >> 3) & 1u) * 16u;

    uint32_t nrowoff = (uint32_t)(warpN * 32) * 128u;

    float acc[NBOP][MA][NPAIR * 2][4];
    #pragma unroll
    for (int b = 0; b < NBOP; ++b)
        #pragma unroll
        for (int m = 0; m < MA; ++m)
            #pragma unroll
            for (int a = 0; a < NPAIR * 2; ++a)
                #pragma unroll
                for (int j = 0; j < 4; ++j) acc[b][m][a][j] = 0.f;

    int st = 0, ph = 0;
    for (int it = 0; it < k_iters; ++it) {
        MBARRIER_WAIT_PARITY(fullb + 8u * st, ph);
        uint32_t sbase = data + st * STAGE_BYTES;
        #pragma unroll
        for (int kk = 0; kk < KCHUNKS; ++kk) {
            // sub-buffer select for TKK=128 (two 64-col chunks)
            uint32_t aoff = (MODE == 0) ? 0u        : (uint32_t)(kk >> 2) * 16384u;
            uint32_t bbas = (MODE == 0) ? 16384u    : 32768u + (uint32_t)(kk >> 2) * 16384u;
            uint32_t kin  = (uint32_t)(kk & 3) * 32u;
            uint32_t kbA = kin + klA;
            uint32_t af[MA][4];
            #pragma unroll
            for (int m = 0; m < MA; ++m)
                ldsm4(af[m], sbase + aoff + rawA + (uint32_t)m * 2048u + (kbA ^ xorA));
            uint32_t kbB = kin + klB;
            #pragma unroll
            for (int b = 0; b < NBOP; ++b) {
                uint32_t bb = sbase + bbas + (uint32_t)b * 16384u + nrowoff + rawB;
                #pragma unroll
                for (int p = 0; p < NPAIR; ++p) {
                    uint32_t br[4];
                    ldsm4(br, bb + (uint32_t)p * 2048u + (kbB ^ xorB));
                    #pragma unroll
                    for (int m = 0; m < MA; ++m) {
                        mma_bf16(acc[b][m][2 * p],     af[m], br[0], br[1]);
                        mma_bf16(acc[b][m][2 * p + 1], af[m], br[2], br[3]);
                    }
                }
            }
        }
        if (lane == 0) MBARRIER_ARRIVE(emptyb + 8u * st);
        if (++st == STAGES) { st = 0; ph ^= 1; }
    }

    // ---------------- epilogue ----------------
    int mrowbase = blockIdx.x * 128 + warpM * 32;
    int ncolbase = blockIdx.y * 128 + warpN * 32;
    int qr = lane >> 2;
    int qc = (lane & 3) * 2;

    #pragma unroll
    for (int matom = 0; matom < MA; ++matom) {
        int r0 = mrowbase + matom * 16 + qr;
        int r1 = r0 + 8;
        float sa0 = s_a[r0], sa1 = s_a[r1];
        if constexpr (MODE == 0) {
            float amax0 = 0.f, amax1 = 0.f;
            #pragma unroll
            for (int a = 0; a < 4; ++a) {
                int n0 = ncolbase + a * 8 + qc;
                float sg0 = s_b0[n0], sg1 = s_b0[n0 + 1];
                float su0 = s_b1[n0], su1 = s_b1[n0 + 1];
                const float* cg = acc[0][matom][a];
                const float* cu = acc[1][matom][a];
                float g00 = cg[0] * sa0 * sg0, g01 = cg[1] * sa0 * sg1;
                float g10 = cg[2] * sa1 * sg0, g11 = cg[3] * sa1 * sg1;
                float u00 = cu[0] * sa0 * su0, u01 = cu[1] * sa0 * su1;
                float u10 = cu[2] * sa1 * su0, u11 = cu[3] * sa1 * su1;
                float h00 = (g00 / (1.f + expf(-g00))) * u00;
                float h01 = (g01 / (1.f + expf(-g01))) * u01;
                float h10 = (g10 / (1.f + expf(-g10))) * u10;
                float h11 = (g11 / (1.f + expf(-g11))) * u11;
                *(float2*)(outp + (size_t)r0 * out_ld + n0) = make_float2(h00, h01);
                *(float2*)(outp + (size_t)r1 * out_ld + n0) = make_float2(h10, h11);
                amax0 = fmaxf(amax0, fmaxf(fabsf(h00), fabsf(h01)));
                amax1 = fmaxf(amax1, fmaxf(fabsf(h10), fabsf(h11)));
            }
            #pragma unroll
            for (int d = 1; d < 4; d <<= 1) {
                amax0 = fmaxf(amax0, __shfl_xor_sync(0xFFFFFFFFu, amax0, d));
                amax1 = fmaxf(amax1, __shfl_xor_sync(0xFFFFFFFFu, amax1, d));
            }
            if ((lane & 3) == 0) {
                atomicMax(rowmax + r0, __float_as_uint(amax0));
                atomicMax(rowmax + r1, __float_as_uint(amax1));
            }
        } else {
            #pragma unroll
            for (int a = 0; a < 4; ++a) {
                int n0 = ncolbase + a * 8 + qc;
                float sw0 = s_b0[n0], sw1 = s_b0[n0 + 1];
                const float* c = acc[0][matom][a];
                *(float2*)(outp + (size_t)r0 * out_ld + n0) =
                    make_float2(c[0] * sa0 * sw0, c[1] * sa0 * sw1);
                *(float2*)(outp + (size_t)r1 * out_ld + n0) =
                    make_float2(c[2] * sa1 * sw0, c[3] * sa1 * sw1);
            }
        }
    }
}

#define GEMM_SMEM0 (4 * 49152u + 2048u)
#define GEMM_SMEM1 (3 * 65536u + 2048u)

// ======================= host side ===========================
typedef CUresult (*tmap_encode_fn)(
    CUtensorMap*, CUtensorMapDataType, cuuint32_t, void*,
    const cuuint64_t*, const cuuint64_t*, const cuuint32_t*, const cuuint32_t*,
    CUtensorMapInterleave, CUtensorMapSwizzle, CUtensorMapL2promotion,
    CUtensorMapFloatOOBfill);

static void make_map(tmap_encode_fn fn, CUtensorMap* map, void* ptr,
                     uint64_t d0, uint64_t d1, uint32_t box_rows) {
    cuuint64_t dims[2]    = {(cuuint64_t)d0, (cuuint64_t)d1};
    cuuint64_t strides[1] = {(cuuint64_t)(d0 * 2)};            // bf16
    cuuint32_t box[2]     = {64u, box_rows};                   // 64 bf16 = 128B (SW128)
    cuuint32_t es[2]      = {1u, 1u};
    fn(map, CU_TENSOR_MAP_DATA_TYPE_BFLOAT16, 2, ptr, dims, strides, box, es,
       CU_TENSOR_MAP_INTERLEAVE_NONE, CU_TENSOR_MAP_SWIZZLE_128B,
       CU_TENSOR_MAP_L2_PROMOTION_L2_128B, CU_TENSOR_MAP_FLOAT_OOB_FILL_NONE);
}

extern "C" void kernel_launch(void* const* d_in, const int* in_sizes, int n_in,
                              void* d_out, int out_size) {
    const float* x  = (const float*)d_in[0];
    const float* wg = (const float*)d_in[1];
    const float* wu = (const float*)d_in[2];
    const float* wd = (const float*)d_in[3];
    float* out = (float*)d_out;

    void *p_xq, *p_wgq, *p_wuq, *p_wdq, *p_h, *p_hq;
    void *p_sx, *p_swg, *p_swu, *p_swd, *p_sh, *p_rm;
    cudaGetSymbolAddress(&p_xq, g_xq);
    cudaGetSymbolAddress(&p_wgq, g_wgq);
    cudaGetSymbolAddress(&p_wuq, g_wuq);
    cudaGetSymbolAddress(&p_wdq, g_wdq);
    cudaGetSymbolAddress(&p_h, g_h);
    cudaGetSymbolAddress(&p_hq, g_hq);
    cudaGetSymbolAddress(&p_sx, g_sx);
    cudaGetSymbolAddress(&p_swg, g_swg);
    cudaGetSymbolAddress(&p_swu, g_swu);
    cudaGetSymbolAddress(&p_swd, g_swd);
    cudaGetSymbolAddress(&p_sh, g_sh);
    cudaGetSymbolAddress(&p_rm, g_rowmax);

    void* fn = nullptr;
    cudaDriverEntryPointQueryResult qres;
    cudaGetDriverEntryPointByVersion("cuTensorMapEncodeTiled", &fn, 12000,
                                     cudaEnableDefault, &qres);
    tmap_encode_fn encode = (tmap_encode_fn)fn;

    CUtensorMap mXQ, mWG, mWU, mHQ, mWD;
    make_map(encode, &mXQ, p_xq,  HID,   MT,    128); // GEMM1 A
    make_map(encode, &mWG, p_wgq, HID,   INTER, 128); // GEMM1 Bgate
    make_map(encode, &mWU, p_wuq, HID,   INTER, 128); // GEMM1 Bup
    make_map(encode, &mHQ, p_hq,  INTER, MT,    128); // GEMM2 A
    make_map(encode, &mWD, p_wdq, INTER, HID,   128); // GEMM2 B

    cudaMemsetAsync(p_rm, 0, MT * sizeof(unsigned int));

    // single merged quant launch for all inputs
    quant_all_kernel<<<MT + 2 * INTER + HID, 256>>>(
        x, wg, wu, wd,
        (__nv_bfloat16*)p_xq, (__nv_bfloat16*)p_wgq, (__nv_bfloat16*)p_wuq,
        (__nv_bfloat16*)p_wdq,
        (float*)p_sx, (float*)p_swg, (float*)p_swu, (float*)p_swd);

    cudaFuncSetAttribute(gemm_kernel<0>, cudaFuncAttributeMaxDynamicSharedMemorySize, GEMM_SMEM0);
    cudaFuncSetAttribute(gemm_kernel<1>, cudaFuncAttributeMaxDynamicSharedMemorySize, GEMM_SMEM1);

    // GEMM1: fused gate/up + SwiGLU -> h. grid 32 x 86, TKK=64, k_iters=64
    gemm_kernel<0><<<dim3(MT / 128, INTER / 128), GEMM_THREADS, GEMM_SMEM0>>>(
        mXQ, mWG, mWU, HID / 64,
        (const float*)p_sx, (const float*)p_swg, (const float*)p_swu,
        (float*)p_h, (unsigned int*)p_rm, INTER);

    quant_h_kernel<<<dim3(MT, 4), 256>>>((const float*)p_h, (const unsigned int*)p_rm,
                                         (__nv_bfloat16*)p_hq, (float*)p_sh);

    // GEMM2: down proj. grid 32 x 32, TKK=128, k_iters=86
    gemm_kernel<1><<<dim3(MT / 128, HID / 128), GEMM_THREADS, GEMM_SMEM1>>>(
        mHQ, mWD, mWD, INTER / 128,
        (const float*)p_sh, (const float*)p_swd, (const float*)p_swd,
        out, nullptr, HID);
}

// round 17
// speedup vs baseline: 1.5369x; 1.0168x over previous
#include <cuda_runtime.h>
#include <cuda_bf16.h>
#include <cuda.h>
#include <cstdint>
#include <cmath>

// ======================= problem sizes =======================
#define MT     4096      // tokens = B*S
#define HID    4096
#define INTER  11008

// ======================= PTX helpers (portable sm_90 subset) =========
__device__ __forceinline__ uint32_t smem_to_u32(const void* smem_ptr) {
    uint32_t addr;
    asm("{ .reg .u64 tmp; cvta.to.shared.u64 tmp, %1; cvt.u32.u64 %0, tmp; }"
        : "=r"(addr) : "l"(smem_ptr));
    return addr;
}

#define MBARRIER_INIT(mbar, count) \
    asm volatile("mbarrier.init.shared.b64 [%0], %1;" \
        :: "r"((uint32_t)(mbar)), "r"((uint32_t)(count)) : "memory")

#define MBARRIER_EXPECT_TX(mbar, tx_bytes) \
    asm volatile("mbarrier.arrive.expect_tx.shared.b64 _, [%0], %1;" \
        :: "r"((uint32_t)(mbar)), "r"((uint32_t)(tx_bytes)) : "memory")

#define MBARRIER_ARRIVE(mbar) \
    asm volatile("mbarrier.arrive.shared.b64 _, [%0];" \
        :: "r"((uint32_t)(mbar)) : "memory")

#define MBARRIER_WAIT_PARITY(mbar, parity) do { \
    uint32_t _mbar = (uint32_t)(mbar); \
    uint32_t _parity = (uint32_t)(parity); \
    uint32_t _done; \
    asm volatile( \
        "{\n\t" \
        ".reg .pred p;\n\t" \
        "mbarrier.try_wait.parity.acquire.cta.shared::cta.b64 p, [%1], %2;\n\t" \
        "selp.b32 %0, 1, 0, p;\n\t" \
        "}" \
        : "=r"(_done) : "r"(_mbar), "r"(_parity) : "memory"); \
    if (!_done) { \
        asm volatile( \
            "{\n\t" \
            ".reg .pred P1;\n\t" \
            "WAIT_LOOP_%=:\n\t" \
            "mbarrier.try_wait.parity.acquire.cta.shared::cta.b64 P1, [%0], %1, 0x989680;\n\t" \
            "@P1 bra.uni WAIT_DONE_%=;\n\t" \
            "bra.uni WAIT_LOOP_%=;\n\t" \
            "WAIT_DONE_%=:\n\t" \
            "}" \
            :: "r"(_mbar), "r"(_parity) : "memory"); \
    } \
} while(0)

#define MBARRIER_WAIT_PARITY_RELAXED(mbar, parity) do { \
    uint32_t _mbar = (uint32_t)(mbar); \
    uint32_t _parity = (uint32_t)(parity); \
    uint32_t _done; \
    asm volatile( \
        "{\n\t" \
        ".reg .pred p;\n\t" \
        "mbarrier.try_wait.parity.relaxed.cta.shared::cta.b64 p, [%1], %2, 0x989680;\n\t" \
        "selp.b32 %0, 1, 0, p;\n\t" \
        "}" \
        : "=r"(_done) : "r"(_mbar), "r"(_parity) : "memory"); \
    if (!_done) { \
        asm volatile( \
            "{\n\t" \
            ".reg .pred P1;\n\t" \
            "WAIT_LOOP_%=:\n\t" \
            "mbarrier.try_wait.parity.relaxed.cta.shared::cta.b64 P1, [%0], %1, 0x989680;\n\t" \
            "@P1 bra.uni WAIT_DONE_%=;\n\t" \
            "bra.uni WAIT_LOOP_%=;\n\t" \
            "WAIT_DONE_%=:\n\t" \
            "}" \
            :: "r"(_mbar), "r"(_parity) : "memory"); \
    } \
} while(0)

__device__ __forceinline__ void tma_load_2d(uint32_t dst, const CUtensorMap* map,
                                            int cx, int cy, uint32_t mbar) {
    asm volatile(
        "cp.async.bulk.tensor.2d.shared::cta.global.tile.mbarrier::complete_tx::bytes "
        "[%0], [%1, {%2, %3}], [%4];"
        :: "r"(dst), "l"(map), "r"(cx), "r"(cy), "r"(mbar) : "memory");
}

__device__ __forceinline__ void ldsm4(uint32_t* r, uint32_t addr) {
    asm volatile("ldmatrix.sync.aligned.m8n8.x4.shared.b16 {%0,%1,%2,%3}, [%4];"
        : "=r"(r[0]), "=r"(r[1]), "=r"(r[2]), "=r"(r[3]) : "r"(addr));
}

__device__ __forceinline__ void mma_bf16(float* c, const uint32_t* a,
                                         uint32_t b0, uint32_t b1) {
    asm volatile("mma.sync.aligned.m16n8k16.row.col.f32.bf16.bf16.f32 "
        "{%0,%1,%2,%3}, {%4,%5,%6,%7}, {%8,%9}, {%0,%1,%2,%3};"
        : "+f"(c[0]), "+f"(c[1]), "+f"(c[2]), "+f"(c[3])
        : "r"(a[0]), "r"(a[1]), "r"(a[2]), "r"(a[3]), "r"(b0), "r"(b1));
}

// ======================= device scratch ======================
__device__ __nv_bfloat16 g_xq[(size_t)MT * HID];
__device__ __nv_bfloat16 g_wgq[(size_t)INTER * HID];
__device__ __nv_bfloat16 g_wuq[(size_t)INTER * HID];
__device__ __nv_bfloat16 g_wdq[(size_t)HID * INTER];
__device__ float         g_h[(size_t)MT * INTER];
__device__ __nv_bfloat16 g_hq[(size_t)MT * INTER];
__device__ float         g_sx[MT];
__device__ float         g_swg[INTER];
__device__ float         g_swu[INTER];
__device__ float         g_swd[HID];
__device__ float         g_sh[MT];
__device__ unsigned int  g_rowmax[MT];

// ======================= quantize kernels ====================
// reciprocal-multiply quantization: rs = 1/sc computed once per row (exact),
// per-element rint(v*rs) replaces per-element division.
__device__ __forceinline__ uint32_t pack_q2r(float a, float b, float rs) {
    float qa = fminf(fmaxf(rintf(a * rs), -128.f), 127.f);
    float qb = fminf(fmaxf(rintf(b * rs), -128.f), 127.f);
    __nv_bfloat162 p = __floats2bfloat162_rn(qa, qb);
    return *(uint32_t*)&p;
}

template<int COLS>
__device__ __forceinline__ void quant_row_body(const float* __restrict__ in,
                                               __nv_bfloat16* __restrict__ q,
                                               float* __restrict__ scale, int row) {
    constexpr int N4  = COLS / 4;
    constexpr int PER = (N4 + 255) / 256;
    __shared__ float red[8];
    int tid = threadIdx.x;
    const float4* r4 = (const float4*)(in + (size_t)row * COLS);
    float4 v[PER];
    float m = 0.f;
    #pragma unroll
    for (int i = 0; i < PER; ++i) {
        int c = tid + i * 256;
        if (c < N4) {
            v[i] = r4[c];
            m = fmaxf(m, fmaxf(fmaxf(fabsf(v[i].x), fabsf(v[i].y)),
                               fmaxf(fabsf(v[i].z), fabsf(v[i].w))));
        }
    }
    #pragma unroll
    for (int d = 16; d > 0; d >>= 1) m = fmaxf(m, __shfl_xor_sync(0xFFFFFFFFu, m, d));
    if ((tid & 31) == 0) red[tid >> 5] = m;
    __syncthreads();
    m = red[0];
    #pragma unroll
    for (int w = 1; w < 8; ++w) m = fmaxf(m, red[w]);
    float sc = fmaxf(m / 127.0f, 1e-8f);
    float rs = 1.0f / sc;                 // exact once-per-row reciprocal
    if (tid == 0) scale[row] = sc;
    uint2* q2 = (uint2*)(q + (size_t)row * COLS);
    #pragma unroll
    for (int i = 0; i < PER; ++i) {
        int c = tid + i * 256;
        if (c < N4) {
            uint2 o;
            o.x = pack_q2r(v[i].x, v[i].y, rs);
            o.y = pack_q2r(v[i].z, v[i].w, rs);
            q2[c] = o;
        }
    }
}

// ALL input quantization in one launch: x, w_gate, w_up (4096-col) + w_down (11008-col)
__global__ __launch_bounds__(256)
void quant_all_kernel(const float* __restrict__ x,  const float* __restrict__ wg,
                      const float* __restrict__ wu, const float* __restrict__ wd,
                      __nv_bfloat16* xq, __nv_bfloat16* wgq, __nv_bfloat16* wuq,
                      __nv_bfloat16* wdq,
                      float* sx, float* swg, float* swu, float* swd) {
    int row = blockIdx.x;
    if (row < MT)                   quant_row_body<HID>(x,  xq,  sx,  row);
    else if (row < MT + INTER)      quant_row_body<HID>(wg, wgq, swg, row - MT);
    else if (row < MT + 2 * INTER)  quant_row_body<HID>(wu, wuq, swu, row - MT - INTER);
    else                            quant_row_body<INTER>(wd, wdq, swd, row - MT - 2 * INTER);
}

// h quant: scale precomputed via rowmax -> no reduction; 4 blocks per row
__global__ __launch_bounds__(256)
void quant_h_kernel(const float* __restrict__ h,
                    const unsigned int* __restrict__ rowmax,
                    __nv_bfloat16* __restrict__ hq,
                    float* __restrict__ sh) {
    int row = blockIdx.x;
    float sc = fmaxf(__uint_as_float(rowmax[row]) / 127.0f, 1e-8f);
    float rs = 1.0f / sc;
    if (threadIdx.x == 0 && blockIdx.y == 0) sh[row] = sc;
    const float4* r4 = (const float4*)(h + (size_t)row * INTER);
    uint2* q2 = (uint2*)(hq + (size_t)row * INTER);
    int chunk = (INTER >> 2) / 4;
    int c0 = blockIdx.y * chunk;
    for (int c = c0 + threadIdx.x; c < c0 + chunk; c += 256) {
        float4 v = r4[c];
        uint2 o;
        o.x = pack_q2r(v.x, v.y, rs);
        o.y = pack_q2r(v.z, v.w, rs);
        q2[c] = o;
    }
}

// ======================= GEMM kernel (R14 best config) =========
// Non-persistent: one CTA per 128x128 tile. 16 math warps (mw=4 x nw=4)
// + 1 producer warp, 544 threads. Each warp 32x32 per bop.
// MODE 0: gate/up (2 B ops). TKK=64.  Stage: [A 16K][Bg 16K][Bu 16K], 4 stages.
// MODE 1: down proj (1 B).   TKK=128. Stage: [A0 16K][A1 16K][B0 16K][B1 16K],
//         3 stages (64KB each).

#define GEMM_THREADS 544

__device__ __forceinline__ float fast_silu(float g) {
    // silu(g) = g / (1 + exp(-g)); MUFU-based exp + fast divide.
    return __fdividef(g, 1.0f + __expf(-g));
}

template<int MODE>
__global__ __launch_bounds__(GEMM_THREADS, 1)
void gemm_kernel(const __grid_constant__ CUtensorMap tma_a,
                 const __grid_constant__ CUtensorMap tma_b0,
                 const __grid_constant__ CUtensorMap tma_b1,
                 int k_iters,
                 const float* __restrict__ s_a,
                 const float* __restrict__ s_b0,
                 const float* __restrict__ s_b1,
                 float* __restrict__ outp,
                 unsigned int* __restrict__ rowmax,
                 int out_ld)
{
    constexpr int      STAGES      = (MODE == 0) ? 4 : 3;
    constexpr uint32_t STAGE_BYTES = (MODE == 0) ? 49152u : 65536u;
    constexpr int      TKK         = (MODE == 0) ? 64 : 128;
    constexpr int      KCHUNKS     = (MODE == 0) ? 4 : 8;

    extern __shared__ char smem[];
    uint32_t sb     = smem_to_u32(smem);
    uint32_t fullb  = sb;            // STAGES x 8B
    uint32_t emptyb = sb + 32u;      // STAGES x 8B
    uint32_t data   = (sb + 64u + 1023u) & ~1023u;

    int tid  = threadIdx.x;
    int wid  = tid >> 5;
    int lane = tid & 31;

    if (tid == 0) {
        #pragma unroll
        for (int s = 0; s < STAGES; s++) {
            MBARRIER_INIT(fullb  + 8u * s, 1);
            MBARRIER_INIT(emptyb + 8u * s, 16);
        }
    }
    __syncthreads();

    // ---------------- producer warp ----------------
    if (wid == 16) {
        if (lane == 0) {
            int mbase = blockIdx.x * 128;
            int nbase = blockIdx.y * 128;
            int st = 0, ph = 1;
            for (int it = 0; it < k_iters; ++it) {
                MBARRIER_WAIT_PARITY_RELAXED(emptyb + 8u * st, ph);
                MBARRIER_EXPECT_TX(fullb + 8u * st, STAGE_BYTES);
                uint32_t d0 = data + st * STAGE_BYTES;
                uint32_t mb = fullb + 8u * st;
                if (MODE == 0) {
                    tma_load_2d(d0,           &tma_a,  it * TKK, mbase, mb);
                    tma_load_2d(d0 + 16384u, &tma_b0, it * TKK, nbase, mb);
                    tma_load_2d(d0 + 32768u, &tma_b1, it * TKK, nbase, mb);
                } else {
                    tma_load_2d(d0,           &tma_a,  it * TKK,      mbase, mb);
                    tma_load_2d(d0 + 16384u, &tma_a,  it * TKK + 64, mbase, mb);
                    tma_load_2d(d0 + 32768u, &tma_b0, it * TKK,      nbase, mb);
                    tma_load_2d(d0 + 49152u, &tma_b0, it * TKK + 64, nbase, mb);
                }
                if (++st == STAGES) { st = 0; ph ^= 1; }
            }
        }
        return;
    }

    // ---------------- math warps 0..15 (mw=4 x nw=4) ----------------
    constexpr int NBOP  = (MODE == 0) ? 2 : 1;
    constexpr int NPAIR = 2;
    constexpr int MA    = 2;

    int warpM = wid >> 2;            // 0..3, 32 rows each
    int warpN = wid & 3;             // 0..3, 32 cols each

    int rA = warpM * 32 + (lane & 15);
    uint32_t rawA = (uint32_t)rA * 128u;
    uint32_t xorA = (uint32_t)(rA & 7) * 16u;
    uint32_t klA  = ((uint32_t)(lane >> 4) & 1u) * 16u;

    uint32_t rbrow = (uint32_t)((lane & 7) + ((lane >> 4) << 3));
    uint32_t rawB  = rbrow * 128u;
    uint32_t xorB  = (uint32_t)(lane & 7) * 16u;
    uint32_t klB   = ((uint32_t)(lane >> 3) & 1u) * 16u;

    uint32_t nrowoff = (uint32_t)(warpN * 32) * 128u;

    float acc[NBOP][MA][NPAIR * 2][4];
    #pragma unroll
    for (int b = 0; b < NBOP; ++b)
        #pragma unroll
        for (int m = 0; m < MA; ++m)
            #pragma unroll
            for (int a = 0; a < NPAIR * 2; ++a)
                #pragma unroll
                for (int j = 0; j < 4; ++j) acc[b][m][a][j] = 0.f;

    int st = 0, ph = 0;
    for (int it = 0; it < k_iters; ++it) {
        MBARRIER_WAIT_PARITY(fullb + 8u * st, ph);
        uint32_t sbase = data + st * STAGE_BYTES;
        #pragma unroll
        for (int kk = 0; kk < KCHUNKS; ++kk) {
            // sub-buffer select for TKK=128 (two 64-col chunks)
            uint32_t aoff = (MODE == 0) ? 0u        : (uint32_t)(kk >> 2) * 16384u;
            uint32_t bbas = (MODE == 0) ? 16384u    : 32768u + (uint32_t)(kk >> 2) * 16384u;
            uint32_t kin  = (uint32_t)(kk & 3) * 32u;
            uint32_t kbA = kin + klA;
            uint32_t af[MA][4];
            #pragma unroll
            for (int m = 0; m < MA; ++m)
                ldsm4(af[m], sbase + aoff + rawA + (uint32_t)m * 2048u + (kbA ^ xorA));
            uint32_t kbB = kin + klB;
            #pragma unroll
            for (int b = 0; b < NBOP; ++b) {
                uint32_t bb = sbase + bbas + (uint32_t)b * 16384u + nrowoff + rawB;
                #pragma unroll
                for (int p = 0; p < NPAIR; ++p) {
                    uint32_t br[4];
                    ldsm4(br, bb + (uint32_t)p * 2048u + (kbB ^ xorB));
                    #pragma unroll
                    for (int m = 0; m < MA; ++m) {
                        mma_bf16(acc[b][m][2 * p],     af[m], br[0], br[1]);
                        mma_bf16(acc[b][m][2 * p + 1], af[m], br[2], br[3]);
                    }
                }
            }
        }
        if (lane == 0) MBARRIER_ARRIVE(emptyb + 8u * st);
        if (++st == STAGES) { st = 0; ph ^= 1; }
    }

    // ---------------- epilogue ----------------
    int mrowbase = blockIdx.x * 128 + warpM * 32;
    int ncolbase = blockIdx.y * 128 + warpN * 32;
    int qr = lane >> 2;
    int qc = (lane & 3) * 2;

    #pragma unroll
    for (int matom = 0; matom < MA; ++matom) {
        int r0 = mrowbase + matom * 16 + qr;
        int r1 = r0 + 8;
        float sa0 = s_a[r0], sa1 = s_a[r1];
        if constexpr (MODE == 0) {
            float amax0 = 0.f, amax1 = 0.f;
            #pragma unroll
            for (int a = 0; a < 4; ++a) {
                int n0 = ncolbase + a * 8 + qc;
                float sg0 = s_b0[n0], sg1 = s_b0[n0 + 1];
                float su0 = s_b1[n0], su1 = s_b1[n0 + 1];
                const float* cg = acc[0][matom][a];
                const float* cu = acc[1][matom][a];
                float g00 = cg[0] * sa0 * sg0, g01 = cg[1] * sa0 * sg1;
                float g10 = cg[2] * sa1 * sg0, g11 = cg[3] * sa1 * sg1;
                float u00 = cu[0] * sa0 * su0, u01 = cu[1] * sa0 * su1;
                float u10 = cu[2] * sa1 * su0, u11 = cu[3] * sa1 * su1;
                float h00 = fast_silu(g00) * u00;
                float h01 = fast_silu(g01) * u01;
                float h10 = fast_silu(g10) * u10;
                float h11 = fast_silu(g11) * u11;
                *(float2*)(outp + (size_t)r0 * out_ld + n0) = make_float2(h00, h01);
                *(float2*)(outp + (size_t)r1 * out_ld + n0) = make_float2(h10, h11);
                amax0 = fmaxf(amax0, fmaxf(fabsf(h00), fabsf(h01)));
                amax1 = fmaxf(amax1, fmaxf(fabsf(h10), fabsf(h11)));
            }
            #pragma unroll
            for (int d = 1; d < 4; d <<= 1) {
                amax0 = fmaxf(amax0, __shfl_xor_sync(0xFFFFFFFFu, amax0, d));
                amax1 = fmaxf(amax1, __shfl_xor_sync(0xFFFFFFFFu, amax1, d));
            }
            if ((lane & 3) == 0) {
                atomicMax(rowmax + r0, __float_as_uint(amax0));
                atomicMax(rowmax + r1, __float_as_uint(amax1));
            }
        } else {
            #pragma unroll
            for (int a = 0; a < 4; ++a) {
                int n0 = ncolbase + a * 8 + qc;
                float sw0 = s_b0[n0], sw1 = s_b0[n0 + 1];
                const float* c = acc[0][matom][a];
                *(float2*)(outp + (size_t)r0 * out_ld + n0) =
                    make_float2(c[0] * sa0 * sw0, c[1] * sa0 * sw1);
                *(float2*)(outp + (size_t)r1 * out_ld + n0) =
                    make_float2(c[2] * sa1 * sw0, c[3] * sa1 * sw1);
            }
        }
    }
}

#define GEMM_SMEM0 (4 * 49152u + 2048u)
#define GEMM_SMEM1 (3 * 65536u + 2048u)

// ======================= host side ===========================
typedef CUresult (*tmap_encode_fn)(
    CUtensorMap*, CUtensorMapDataType, cuuint32_t, void*,
    const cuuint64_t*, const cuuint64_t*, const cuuint32_t*, const cuuint32_t*,
    CUtensorMapInterleave, CUtensorMapSwizzle, CUtensorMapL2promotion,
    CUtensorMapFloatOOBfill);

static void make_map(tmap_encode_fn fn, CUtensorMap* map, void* ptr,
                     uint64_t d0, uint64_t d1, uint32_t box_rows) {
    cuuint64_t dims[2]    = {(cuuint64_t)d0, (cuuint64_t)d1};
    cuuint64_t strides[1] = {(cuuint64_t)(d0 * 2)};            // bf16
    cuuint32_t box[2]     = {64u, box_rows};                   // 64 bf16 = 128B (SW128)
    cuuint32_t es[2]      = {1u, 1u};
    fn(map, CU_TENSOR_MAP_DATA_TYPE_BFLOAT16, 2, ptr, dims, strides, box, es,
       CU_TENSOR_MAP_INTERLEAVE_NONE, CU_TENSOR_MAP_SWIZZLE_128B,
       CU_TENSOR_MAP_L2_PROMOTION_L2_128B, CU_TENSOR_MAP_FLOAT_OOB_FILL_NONE);
}

extern "C" void kernel_launch(void* const* d_in, const int* in_sizes, int n_in,
                              void* d_out, int out_size) {
    const float* x  = (const float*)d_in[0];
    const float* wg = (const float*)d_in[1];
    const float* wu = (const float*)d_in[2];
    const float* wd = (const float*)d_in[3];
    float* out = (float*)d_out;

    void *p_xq, *p_wgq, *p_wuq, *p_wdq, *p_h, *p_hq;
    void *p_sx, *p_swg, *p_swu, *p_swd, *p_sh, *p_rm;
    cudaGetSymbolAddress(&p_xq, g_xq);
    cudaGetSymbolAddress(&p_wgq, g_wgq);
    cudaGetSymbolAddress(&p_wuq, g_wuq);
    cudaGetSymbolAddress(&p_wdq, g_wdq);
    cudaGetSymbolAddress(&p_h, g_h);
    cudaGetSymbolAddress(&p_hq, g_hq);
    cudaGetSymbolAddress(&p_sx, g_sx);
    cudaGetSymbolAddress(&p_swg, g_swg);
    cudaGetSymbolAddress(&p_swu, g_swu);
    cudaGetSymbolAddress(&p_swd, g_swd);
    cudaGetSymbolAddress(&p_sh, g_sh);
    cudaGetSymbolAddress(&p_rm, g_rowmax);

    void* fn = nullptr;
    cudaDriverEntryPointQueryResult qres;
    cudaGetDriverEntryPointByVersion("cuTensorMapEncodeTiled", &fn, 12000,
                                     cudaEnableDefault, &qres);
    tmap_encode_fn encode = (tmap_encode_fn)fn;

    CUtensorMap mXQ, mWG, mWU, mHQ, mWD;
    make_map(encode, &mXQ, p_xq,  HID,   MT,    128); // GEMM1 A
    make_map(encode, &mWG, p_wgq, HID,   INTER, 128); // GEMM1 Bgate
    make_map(encode, &mWU, p_wuq, HID,   INTER, 128); // GEMM1 Bup
    make_map(encode, &mHQ, p_hq,  INTER, MT,    128); // GEMM2 A
    make_map(encode, &mWD, p_wdq, INTER, HID,   128); // GEMM2 B

    cudaMemsetAsync(p_rm, 0, MT * sizeof(unsigned int));

    // single merged quant launch for all inputs
    quant_all_kernel<<<MT + 2 * INTER + HID, 256>>>(
        x, wg, wu, wd,
        (__nv_bfloat16*)p_xq, (__nv_bfloat16*)p_wgq, (__nv_bfloat16*)p_wuq,
        (__nv_bfloat16*)p_wdq,
        (float*)p_sx, (float*)p_swg, (float*)p_swu, (float*)p_swd);

    cudaFuncSetAttribute(gemm_kernel<0>, cudaFuncAttributeMaxDynamicSharedMemorySize, GEMM_SMEM0);
    cudaFuncSetAttribute(gemm_kernel<1>, cudaFuncAttributeMaxDynamicSharedMemorySize, GEMM_SMEM1);

    // GEMM1: fused gate/up + SwiGLU -> h. grid 32 x 86, TKK=64, k_iters=64
    gemm_kernel<0><<<dim3(MT / 128, INTER / 128), GEMM_THREADS, GEMM_SMEM0>>>(
        mXQ, mWG, mWU, HID / 64,
        (const float*)p_sx, (const float*)p_swg, (const float*)p_swu,
        (float*)p_h, (unsigned int*)p_rm, INTER);

    quant_h_kernel<<<dim3(MT, 4), 256>>>((const float*)p_h, (const unsigned int*)p_rm,
                                         (__nv_bfloat16*)p_hq, (float*)p_sh);

    // GEMM2: down proj. grid 32 x 32, TKK=128, k_iters=86
    gemm_kernel<1><<<dim3(MT / 128, HID / 128), GEMM_THREADS, GEMM_SMEM1>>>(
        mHQ, mWD, mWD, INTER / 128,
        (const float*)p_sh, (const float*)p_swd, (const float*)p_swd,
        out, nullptr, HID);
}